// round 15
// baseline (speedup 1.0000x reference)
#include <cuda_runtime.h>
#include <math.h>
#include <stdint.h>

#define BB 16
#define GG 100
#define PP 8400
#define CC 80
#define TK 13
#define NBIN 64   // 8x8 spatial bins
#define NCHMAX ((PP + 31) / 32)

// ---------------- static scratch ----------------
__device__ int           d_fgpre[BB * PP];
__device__ int           d_mcount[BB * PP];
__device__ int           d_mg[BB * PP];
__device__ unsigned char d_valid[BB * PP];
__device__ float4        d_sorted[BB * PP];
__device__ int4          d_cmeta[BB * NCHMAX];   // float-bits, atomically min/maxed
__device__ int           d_bincnt[BB * NBIN];    // zero-initialized; re-zeroed each run by inv13
__device__ int           d_bincur[BB * NBIN];
__device__ int           d_inv13[BB * TK];
__device__ int           d_invcnt[BB];

// ---------------- sorted-list helpers ----------
template <int N>
__device__ __forceinline__ void ins_desc(float (&V)[N], int (&I)[N], float v, int idx) {
    if (v > V[N - 1] || (v == V[N - 1] && idx < I[N - 1])) {
#pragma unroll
        for (int k = 0; k < N; k++) {
            if (v > V[k] || (v == V[k] && idx < I[k])) {
                float tv = V[k]; int ti = I[k];
                V[k] = v; I[k] = idx;
                v = tv; idx = ti;
            }
        }
    }
}

template <int N>
__device__ __forceinline__ void ins_asc(float (&V)[N], int (&I)[N], float v, int idx) {
    if (v < V[N - 1] || (v == V[N - 1] && idx < I[N - 1])) {
#pragma unroll
        for (int k = 0; k < N; k++) {
            if (v < V[k] || (v == V[k] && idx < I[k])) {
                float tv = V[k]; int ti = I[k];
                V[k] = v; I[k] = idx;
                v = tv; idx = ti;
            }
        }
    }
}

template <int N>
__device__ __forceinline__ void ins_val(float (&V)[N], float v) {
    if (v > V[N - 1]) {
#pragma unroll
        for (int k = 0; k < N; k++) {
            if (v > V[k]) { float tv = V[k]; V[k] = v; v = tv; }
        }
    }
}

__device__ __forceinline__ float skip_radius2(float thr) {
    float rr = 3.0f + log10f(thr + 1e-6f) + 1e-3f;
    if (rr > 0.0f) return rr * rr;
    return (thr < 9e-4f) ? -1.0f : __int_as_float(0x7f800000);
}

__device__ __forceinline__ int binof(float4 t) {
    float xc = 0.5f * (t.x + t.z);
    float yc = 0.5f * (t.y + t.w);
    int bx = min(7, max(0, (int)(xc * (8.0f / 640.0f))));
    int by = min(7, max(0, (int)(yc * (8.0f / 640.0f))));
    return by * 8 + bx;
}

// block merge of 128 sorted ascending lists (value asc, idx asc)
__device__ __forceinline__ void merge_asc(float* s_v, int* s_i, int tid) {
    for (int off = 64; off >= 1; off >>= 1) {
        if (tid < off) {
            float ov[TK]; int oi[TK];
            int ia = tid * TK, ib = (tid + off) * TK, i = 0, j = 0;
#pragma unroll
            for (int k = 0; k < TK; k++) {
                float va = s_v[ia + i], vb = s_v[ib + j];
                int   na = s_i[ia + i], nb = s_i[ib + j];
                bool ta = (va < vb) || (va == vb && na < nb);
                if (ta) { ov[k] = va; oi[k] = na; i++; }
                else    { ov[k] = vb; oi[k] = nb; j++; }
            }
#pragma unroll
            for (int k = 0; k < TK; k++) { s_v[ia + k] = ov[k]; s_i[ia + k] = oi[k]; }
        }
        __syncthreads();
    }
}

// ---------------- prep kernels ----------------
// per (b,p): zero scratch, count bins via shared-aggregated histogram.
__global__ void init_kernel(const float* __restrict__ pred_bboxes, int Pn) {
    int b = blockIdx.y;
    int p = blockIdx.x * blockDim.x + threadIdx.x;
    __shared__ int scnt[NBIN];
    if (threadIdx.x < NBIN) scnt[threadIdx.x] = 0;
    __syncthreads();
    if (p < Pn) {
        int bp = b * Pn + p;
        d_valid[bp]  = 0;
        d_fgpre[bp]  = 0;
        d_mcount[bp] = 0;
        float4 t = reinterpret_cast<const float4*>(pred_bboxes)[(size_t)b * Pn + p];
        atomicAdd(&scnt[binof(t)], 1);
    }
    __syncthreads();
    if (threadIdx.x < NBIN) {
        int c = scnt[threadIdx.x];
        if (c > 0) atomicAdd(&d_bincnt[b * NBIN + threadIdx.x], c);
    }
}

// per (g,b): mark priors strictly inside the gt box via analytic grid rectangles.
__global__ void validrect_kernel(const float* __restrict__ gtb,
                                 const float* __restrict__ pad,
                                 int Pn, int Gn) {
    int g = blockIdx.x, b = blockIdx.y;
    if (pad[b * Gn + g] == 0.0f) return;
    const float gx1 = gtb[(b * Gn + g) * 4 + 0];
    const float gy1 = gtb[(b * Gn + g) * 4 + 1];
    const float gx2 = gtb[(b * Gn + g) * 4 + 2];
    const float gy2 = gtb[(b * Gn + g) * 4 + 3];
    const int   LW[3] = {80, 40, 20};
    const float LS[3] = {8.0f, 16.0f, 32.0f};
    const int   LBASE[3] = {0, 6400, 8000};
    unsigned char* vm = d_valid + b * Pn;
    int tid = threadIdx.x;
#pragma unroll
    for (int lvl = 0; lvl < 3; lvl++) {
        int W = LW[lvl]; float s = LS[lvl]; int base = LBASE[lvl];
        float inv_s = 1.0f / s;
        int c0 = max(0, (int)floorf(gx1 * inv_s - 0.5f));
        int c1 = min(W - 1, (int)ceilf(gx2 * inv_s - 0.5f));
        int r0 = max(0, (int)floorf(gy1 * inv_s - 0.5f));
        int r1 = min(W - 1, (int)ceilf(gy2 * inv_s - 0.5f));
        int nc = c1 - c0 + 1, nr = r1 - r0 + 1;
        if (nc <= 0 || nr <= 0) continue;
        int tot = nc * nr;
        for (int i = tid; i < tot; i += 128) {
            int rr = i / nc, cc = i - rr * nc;
            int col = c0 + cc, row = r0 + rr;
            float px = ((float)col + 0.5f) * s;
            float py = ((float)row + 0.5f) * s;
            if (px > gx1 && px < gx2 && py > gy1 && py < gy2)
                vm[base + row * W + col] = 1;
        }
    }
}

// per-batch: (a) first-13 invalid indices, (b) bin prefix scan + bincnt reset,
// (c) chunk-meta init. One block per batch, 128 threads.
__global__ void inv13_kernel(int Pn, int nch) {
    int b = blockIdx.x, tid = threadIdx.x;

    __shared__ int sb[NBIN];
    int cnt0 = 0;
    if (tid < NBIN) { cnt0 = d_bincnt[b * NBIN + tid]; sb[tid] = cnt0; }
    __syncthreads();
    for (int off = 1; off < NBIN; off <<= 1) {
        int v = 0;
        if (tid < NBIN && tid >= off) v = sb[tid - off];
        __syncthreads();
        if (tid < NBIN) sb[tid] += v;
        __syncthreads();
    }
    if (tid < NBIN) {
        d_bincur[b * NBIN + tid] = sb[tid] - cnt0;   // exclusive prefix
        d_bincnt[b * NBIN + tid] = 0;                // clean for next graph replay
    }

    for (int i = tid; i < nch; i += 128)
        d_cmeta[b * NCHMAX + i] = make_int4(0x7fffffff, 0x7fffffff, 0x80000000, 0x80000000);

    int lst[TK]; int cnt = 0;
    for (int p = tid; p < Pn && cnt < TK; p += 128)
        if (!d_valid[b * Pn + p]) lst[cnt++] = p;
#pragma unroll
    for (int k = 0; k < TK; k++) if (k >= cnt) lst[k] = 0x7fffffff;
    __shared__ int s_i[128 * TK];
#pragma unroll
    for (int k = 0; k < TK; k++) s_i[tid * TK + k] = lst[k];
    __syncthreads();
    for (int off = 64; off >= 1; off >>= 1) {
        if (tid < off) {
            int oi[TK];
            int ia = tid * TK, ib = (tid + off) * TK, i = 0, j = 0;
#pragma unroll
            for (int k = 0; k < TK; k++) {
                int na = s_i[ia + i], nb = s_i[ib + j];
                if (na <= nb) { oi[k] = na; i++; } else { oi[k] = nb; j++; }
            }
#pragma unroll
            for (int k = 0; k < TK; k++) s_i[ia + k] = oi[k];
        }
        __syncthreads();
    }
    if (tid == 0) {
        int S = 0;
#pragma unroll
        for (int k = 0; k < TK; k++) {
            d_inv13[b * TK + k] = s_i[k];
            if (s_i[k] != 0x7fffffff) S++;
        }
        d_invcnt[b] = S;
    }
}

// scatter + fused chunk-bbox accumulation; two-level bin reservation
__global__ void scatter_kernel(const float* __restrict__ pred_bboxes, int Pn) {
    int b = blockIdx.y;
    int p = blockIdx.x * blockDim.x + threadIdx.x;
    __shared__ int scnt[NBIN];
    __shared__ int sbase[NBIN];
    if (threadIdx.x < NBIN) scnt[threadIdx.x] = 0;
    __syncthreads();
    float4 t = make_float4(0.f, 0.f, 0.f, 0.f);
    int bin = 0, rank = 0;
    bool act = (p < Pn);
    if (act) {
        t = reinterpret_cast<const float4*>(pred_bboxes)[(size_t)b * Pn + p];
        bin = binof(t);
        rank = atomicAdd(&scnt[bin], 1);
    }
    __syncthreads();
    if (threadIdx.x < NBIN) {
        int c = scnt[threadIdx.x];
        if (c > 0) sbase[threadIdx.x] = atomicAdd(&d_bincur[b * NBIN + threadIdx.x], c);
    }
    __syncthreads();
    if (act) {
        int pos = sbase[bin] + rank;
        d_sorted[b * Pn + pos] = t;
        int4* m = &d_cmeta[b * NCHMAX + (pos >> 5)];
        atomicMin(&m->x, __float_as_int(t.x));
        atomicMin(&m->y, __float_as_int(t.y));
        atomicMax(&m->z, __float_as_int(t.z));
        atomicMax(&m->w, __float_as_int(t.w));
    }
}

// ---------------- main pair kernel ----------------
__global__ __launch_bounds__(128) void pair_kernel(
    const float* __restrict__ pred_bboxes,
    const float* __restrict__ pred_scores,
    const float* __restrict__ priors,
    const int*   __restrict__ gt_labels,
    const float* __restrict__ gt_bboxes,
    const float* __restrict__ pad,
    int Pn, int Gn, int Cn, int nch) {
    int g = blockIdx.x, b = blockIdx.y;
    if (pad[b * Gn + g] == 0.0f) return;

    const float gx1 = gt_bboxes[(b * Gn + g) * 4 + 0];
    const float gy1 = gt_bboxes[(b * Gn + g) * 4 + 1];
    const float gx2 = gt_bboxes[(b * Gn + g) * 4 + 2];
    const float gy2 = gt_bboxes[(b * Gn + g) * 4 + 3];
    const int   cid = gt_labels[b * Gn + g];
    const float ga  = (gx2 - gx1) * (gy2 - gy1);
    const float cx  = (gx1 + gx2) * 0.5f;
    const float cy  = (gy1 + gy2) * 0.5f;

    const float4*        pb  = reinterpret_cast<const float4*>(pred_bboxes) + (size_t)b * Pn;
    const float4*        pr4 = reinterpret_cast<const float4*>(priors);
    const float*         sc  = pred_scores + (size_t)b * Pn * Cn + cid;
    const unsigned char* vm  = d_valid + b * Pn;
    const int tid = threadIdx.x;
    const int warp = tid >> 5, lane = tid & 31;
    const float INFF = __int_as_float(0x7f800000);

    __shared__ float s_v[128 * TK];
    __shared__ int   s_i[128 * TK];
    __shared__ int   s_ks;
    __shared__ int   s_npos;
    __shared__ int   s_need2;

    // ======== Phase 1: top-13 iou; lane-parallel chunk-meta scan ========
    {
        float iv[TK];
#pragma unroll
        for (int k = 0; k < TK; k++) iv[k] = -INFF;
        const float4* sp = d_sorted + (size_t)b * Pn;
        const int4*   cm = d_cmeta + b * NCHMAX;
        int nbatch = (nch + 31) >> 5;
        for (int t = warp; t < nbatch; t += 4) {
            int cbase = t << 5;
            int c = cbase + lane;
            bool hit = false;
            if (c < nch) {
                int4 m4 = cm[c];
                float mx1 = __int_as_float(m4.x), my1 = __int_as_float(m4.y);
                float mx2 = __int_as_float(m4.z), my2 = __int_as_float(m4.w);
                hit = (mx1 < gx2 && mx2 > gx1 && my1 < gy2 && my2 > gy1);
            }
            unsigned mask = __ballot_sync(0xffffffffu, hit);
            while (mask) {
                int bit = __ffs(mask) - 1; mask &= mask - 1;
                int p = ((cbase + bit) << 5) + lane;
                if (p < Pn) {
                    float4 t4 = sp[p];
                    float pa = (t4.z - t4.x) * (t4.w - t4.y);
                    float w = fmaxf(fminf(gx2, t4.z) - fmaxf(gx1, t4.x), 0.0f);
                    float h = fmaxf(fminf(gy2, t4.w) - fmaxf(gy1, t4.y), 0.0f);
                    float inter = w * h;
                    float iou = __fdividef(inter, fmaxf(ga + pa - inter, 1e-6f));
                    ins_val(iv, iou);
                }
            }
        }
#pragma unroll
        for (int k = 0; k < TK; k++) s_v[tid * TK + k] = iv[k];
        __syncthreads();
        for (int off = 64; off >= 1; off >>= 1) {
            if (tid < off) {
                float ov[TK];
                int ia = tid * TK, ib = (tid + off) * TK, i = 0, j = 0;
#pragma unroll
                for (int k = 0; k < TK; k++) {
                    float va = s_v[ia + i], vb = s_v[ib + j];
                    if (va >= vb) { ov[k] = va; i++; } else { ov[k] = vb; j++; }
                }
#pragma unroll
                for (int k = 0; k < TK; k++) s_v[ia + k] = ov[k];
            }
            __syncthreads();
        }
        if (tid == 0) {
            float sum = 0.0f;
#pragma unroll
            for (int k = 0; k < TK; k++) sum += fmaxf(s_v[k], 0.0f);  // skipped pairs are iou==0
            int ks = (int)sum;
            if (ks < 1) ks = 1;
            if (ks > TK) ks = TK;
            s_ks = ks;
        }
        __syncthreads();
    }

    const int   LW[3] = {80, 40, 20};
    const float LS[3] = {8.0f, 16.0f, 32.0f};
    const int   LBASE[3] = {0, 6400, 8000};

    // ======== Phase 2: metric top-13 via gt-box grid rectangle ========
    {
        float mv[TK]; int mi[TK];
#pragma unroll
        for (int k = 0; k < TK; k++) { mv[k] = -INFF; mi[k] = 0x7fffffff; }
#pragma unroll
        for (int lvl = 0; lvl < 3; lvl++) {
            int W = LW[lvl]; float s = LS[lvl]; int base = LBASE[lvl];
            float inv_s = 1.0f / s;
            int c0 = max(0, (int)floorf(gx1 * inv_s - 0.5f));
            int c1 = min(W - 1, (int)ceilf(gx2 * inv_s - 0.5f));
            int r0 = max(0, (int)floorf(gy1 * inv_s - 0.5f));
            int r1 = min(W - 1, (int)ceilf(gy2 * inv_s - 0.5f));
            int nc = c1 - c0 + 1, nr = r1 - r0 + 1;
            if (nc <= 0 || nr <= 0) continue;
            int tot = nc * nr;
            for (int i = tid; i < tot; i += 128) {
                int rr = i / nc, cc = i - rr * nc;
                int col = c0 + cc, row = r0 + rr;
                float px = ((float)col + 0.5f) * s;
                float py = ((float)row + 0.5f) * s;
                if (px > gx1 && px < gx2 && py > gy1 && py < gy2) {
                    int p = base + row * W + col;
                    float4 t = pb[p];
                    float pa = (t.z - t.x) * (t.w - t.y);
                    float w = fmaxf(fminf(gx2, t.z) - fmaxf(gx1, t.x), 0.0f);
                    float h = fmaxf(fminf(gy2, t.w) - fmaxf(gy1, t.y), 0.0f);
                    float inter = w * h;
                    if (inter > 0.0f) {
                        float iou = inter / fmaxf(ga + pa - inter, 1e-6f);
                        float x = sc[(size_t)p * Cn];
                        float ax = fabsf(x);
                        float tt = expf(-ax);
                        float inv = 1.0f / (1.0f + tt);
                        float sig = (x >= 0.0f) ? inv : tt * inv;
                        float i2 = iou * iou;
                        float metric = sig * (i2 * i2 * i2);
                        ins_desc(mv, mi, metric, p);
                    }
                }
            }
        }
#pragma unroll
        for (int k = 0; k < TK; k++) { s_v[tid * TK + k] = mv[k]; s_i[tid * TK + k] = mi[k]; }
        __syncthreads();
        for (int off = 64; off >= 1; off >>= 1) {
            if (tid < off) {
                float ov[TK]; int oi[TK];
                int ia = tid * TK, ib = (tid + off) * TK, i = 0, j = 0;
#pragma unroll
                for (int k = 0; k < TK; k++) {
                    float va = s_v[ia + i], vb = s_v[ib + j];
                    int   na = s_i[ia + i], nb = s_i[ib + j];
                    bool ta = (va > vb) || (va == vb && na < nb);
                    if (ta) { ov[k] = va; oi[k] = na; i++; }
                    else    { ov[k] = vb; oi[k] = nb; j++; }
                }
#pragma unroll
                for (int k = 0; k < TK; k++) { s_v[ia + k] = ov[k]; s_i[ia + k] = oi[k]; }
            }
            __syncthreads();
        }
        if (tid == 0) {
            int np = 0;
#pragma unroll
            for (int k = 0; k < TK; k++) if (s_v[k] > 0.0f) np++;
            s_npos = np;
        }
        __syncthreads();
        if (tid < s_npos) {
            atomicAdd(&d_fgpre[b * Pn + s_i[tid]], 1);
        }
        if (tid == 0 && s_npos < TK) {
            // zero-metric fill: smallest global indices with metric==0; ing ones count
            int need = TK - s_npos;
            for (int p = 0; p < Pn && need > 0; p++) {
                float4 pr = pr4[p];
                bool ing = (pr.x > gx1) && (pr.x < gx2) && (pr.y > gy1) && (pr.y < gy2);
                bool pos = false;
                if (ing) {
                    float4 t = pb[p];
                    float pa = (t.z - t.x) * (t.w - t.y);
                    float w = fmaxf(fminf(gx2, t.z) - fmaxf(gx1, t.x), 0.0f);
                    float h = fmaxf(fminf(gy2, t.w) - fmaxf(gy1, t.y), 0.0f);
                    float inter = w * h;
                    if (inter > 0.0f) {
                        float iou = inter / fmaxf(ga + pa - inter, 1e-6f);
                        float x = sc[(size_t)p * Cn];
                        float ax = fabsf(x);
                        float tt = expf(-ax);
                        float inv = 1.0f / (1.0f + tt);
                        float sig = (x >= 0.0f) ? inv : tt * inv;
                        float i2 = iou * iou;
                        pos = (sig * (i2 * i2 * i2)) > 0.0f;
                    }
                }
                if (!pos) {
                    need--;
                    if (ing) atomicAdd(&d_fgpre[b * Pn + p], 1);
                }
            }
        }
        __syncthreads();
    }

    // ======== Phase 3: cost min-13, two-pass radius ========
    {
        float cv[TK]; int ci[TK];
#pragma unroll
        for (int k = 0; k < TK; k++) { cv[k] = INFF; ci[k] = 0x7fffffff; }
        const int S = d_invcnt[b];
        const bool fast = (S >= TK);
        const float R1 = 5.0013f;    // pass-1 radius (strides)
        const float R2 = 11.0013f;   // full radius: cost beyond > 1e8 sentinel

        if (fast) {
            for (int pass = 0; pass < 2; pass++) {
#pragma unroll
                for (int lvl = 0; lvl < 3; lvl++) {
                    int W = LW[lvl]; float s = LS[lvl]; int base = LBASE[lvl];
                    float inv_s = 1.0f / s;
                    float fc = cx * inv_s - 0.5f, fr = cy * inv_s - 0.5f;
                    float Rb = (pass == 0) ? R1 : R2;
                    int c0 = max(0, (int)floorf(fc - Rb));
                    int c1 = min(W - 1, (int)ceilf(fc + Rb));
                    int r0 = max(0, (int)floorf(fr - Rb));
                    int r1 = min(W - 1, (int)ceilf(fr + Rb));
                    int nc = c1 - c0 + 1, nr = r1 - r0 + 1;
                    if (nc <= 0 || nr <= 0) continue;
                    int tot = nc * nr;
                    float lim1 = R1 * R1 * s * s;
                    float lim2 = R2 * R2 * s * s;
                    for (int i = tid; i < tot; i += 128) {
                        int rr = i / nc, cc = i - rr * nc;
                        int col = c0 + cc, row = r0 + rr;
                        float px = ((float)col + 0.5f) * s;
                        float py = ((float)row + 0.5f) * s;
                        float dx = px - cx, dy = py - cy;
                        float d2 = dx * dx + dy * dy;
                        if (pass == 0) { if (d2 > lim1) continue; }
                        else           { if (d2 <= lim1 || d2 > lim2) continue; }
                        int p = base + row * W + col;
                        if (!vm[p]) continue;
                        float4 t = pb[p];
                        float pa = (t.z - t.x) * (t.w - t.y);
                        float w = fmaxf(fminf(gx2, t.z) - fmaxf(gx1, t.x), 0.0f);
                        float h = fmaxf(fminf(gy2, t.w) - fmaxf(gy1, t.y), 0.0f);
                        float inter = w * h;
                        float iou = inter / fmaxf(ga + pa - inter, 1e-6f);
                        float x = sc[(size_t)p * Cn];
                        float ax = fabsf(x);
                        float tt = expf(-ax);
                        float inv = 1.0f / (1.0f + tt);
                        float sig = (x >= 0.0f) ? inv : tt * inv;
                        float sp = fmaxf(x, 0.0f) + log1pf(tt);
                        float sca = iou - sig;
                        float cls = (sp - x * iou) * (sca * sca);
                        float icst = -3.0f * logf(iou + 1e-7f);
                        float dist = sqrtf(d2) / s;
                        float scp = expf((dist - 3.0f) * 2.302585092994046f);
                        ins_asc(cv, ci, cls + icst + scp, p);
                    }
                }

                // merge (and sentinel-merge) after this pass
#pragma unroll
                for (int k = 0; k < TK; k++) { s_v[tid * TK + k] = cv[k]; s_i[tid * TK + k] = ci[k]; }
                __syncthreads();
                merge_asc(s_v, s_i, tid);
                if (tid == 0) {
                    float av[TK]; int ai[TK];
#pragma unroll
                    for (int k = 0; k < TK; k++) { av[k] = s_v[k]; ai[k] = s_i[k]; }
                    int i = 0, j = 0;
#pragma unroll
                    for (int k = 0; k < TK; k++) {
                        float va = (i < TK) ? av[i] : INFF;
                        int   na = (i < TK) ? ai[i] : 0x7fffffff;
                        float vb = 1e8f;
                        int   nb = d_inv13[b * TK + j];
                        bool ta = (va < vb) || (va == vb && na < nb);
                        if (ta) { s_v[k] = va; s_i[k] = na; i++; }
                        else    { s_v[k] = vb; s_i[k] = nb; j++; }
                    }
                    // pass-1 sufficiency: priors beyond R1 have cost >= thr13?
                    s_need2 = (pass == 0 && skip_radius2(s_v[TK - 1]) > R1 * R1) ? 1 : 0;
                }
                __syncthreads();
                if (!s_need2) break;
            }
        } else {
            for (int p = tid; p < Pn; p += 128) {
                if (vm[p]) {
                    float4 pr = pr4[p];
                    float4 t = pb[p];
                    float pa = (t.z - t.x) * (t.w - t.y);
                    float w = fmaxf(fminf(gx2, t.z) - fmaxf(gx1, t.x), 0.0f);
                    float h = fmaxf(fminf(gy2, t.w) - fmaxf(gy1, t.y), 0.0f);
                    float inter = w * h;
                    float iou = inter / fmaxf(ga + pa - inter, 1e-6f);
                    float x = sc[(size_t)p * Cn];
                    float ax = fabsf(x);
                    float tt = expf(-ax);
                    float inv = 1.0f / (1.0f + tt);
                    float sig = (x >= 0.0f) ? inv : tt * inv;
                    float sp = fmaxf(x, 0.0f) + log1pf(tt);
                    float sca = iou - sig;
                    float cls = (sp - x * iou) * (sca * sca);
                    float icst = -3.0f * logf(iou + 1e-7f);
                    float dx = pr.x - cx, dy = pr.y - cy;
                    float dist = sqrtf(dx * dx + dy * dy) / pr.z;
                    float scp = expf((dist - 3.0f) * 2.302585092994046f);
                    ins_asc(cv, ci, cls + icst + scp, p);
                } else {
                    ins_asc(cv, ci, 1e8f, p);
                }
            }
#pragma unroll
            for (int k = 0; k < TK; k++) { s_v[tid * TK + k] = cv[k]; s_i[tid * TK + k] = ci[k]; }
            __syncthreads();
            merge_asc(s_v, s_i, tid);
        }

        if (tid < s_ks) {
            int p = s_i[tid];
            atomicAdd(&d_mcount[b * Pn + p], 1);
            d_mg[b * Pn + p] = g;
        }
    }
}

// ---------------- final resolution ----------------
__device__ __forceinline__ float cost_of_pair(
    float iou, float x, float d2, float s) {
    float ax  = fabsf(x);
    float t   = expf(-ax);
    float inv = 1.0f / (1.0f + t);
    float sig = (x >= 0.0f) ? inv : t * inv;
    float sp  = fmaxf(x, 0.0f) + log1pf(t);
    float sca = iou - sig;
    float cls = (sp - x * iou) * (sca * sca);
    float icst = -3.0f * logf(iou + 1e-7f);
    float dist = sqrtf(d2) / s;
    float scp  = expf((dist - 3.0f) * 2.302585092994046f);
    return cls + icst + scp;
}

__global__ __launch_bounds__(128) void final_kernel(
    const float* __restrict__ pred_bboxes,
    const float* __restrict__ pred_scores,
    const float* __restrict__ priors,
    const int*   __restrict__ gt_labels,
    const float* __restrict__ gt_bboxes,
    float* __restrict__ out,
    int Pn, int Gn, int Cn, int Bn) {
    int b = blockIdx.y;
    __shared__ float4 sgt[GG];
    __shared__ int    slab[GG];
    for (int i = threadIdx.x; i < Gn; i += blockDim.x) {
        sgt[i]  = reinterpret_cast<const float4*>(gt_bboxes + (size_t)b * Gn * 4)[i];
        slab[i] = gt_labels[b * Gn + i];
    }
    __syncthreads();

    int p = blockIdx.x * blockDim.x + threadIdx.x;
    if (p >= Pn) return;
    int bp = b * Pn + p;
    int BP = Bn * Pn;

    int cnt = d_mcount[bp];
    float lab = 80.0f, metr = 0.0f;
    float4 obox = make_float4(0.f, 0.f, 0.f, 0.f);

    if (cnt > 0) {
        float4 pbx = reinterpret_cast<const float4*>(pred_bboxes + (size_t)b * Pn * 4)[p];
        float pa = (pbx.z - pbx.x) * (pbx.w - pbx.y);
        int gsel;
        if (cnt == 1) {
            gsel = d_mg[bp];
        } else if (!d_valid[bp]) {
            gsel = 0;
        } else {
            float px = priors[p * 4 + 0], py = priors[p * 4 + 1], s = priors[p * 4 + 2];
            float s2 = s * s;
            const float* srow = pred_scores + ((size_t)b * Pn + p) * Cn;
            float best = __int_as_float(0x7f800000);
            float rr2  = __int_as_float(0x7f800000);
            int bg = 0;
            for (int g = 0; g < Gn; g++) {
                float4 gb = sgt[g];
                float gcx = (gb.x + gb.z) * 0.5f, gcy = (gb.y + gb.w) * 0.5f;
                float dx = px - gcx, dy = py - gcy;
                float d2 = dx * dx + dy * dy;
                if (d2 > rr2 * s2) continue;
                float gaa = (gb.z - gb.x) * (gb.w - gb.y);
                float w = fmaxf(fminf(gb.z, pbx.z) - fmaxf(gb.x, pbx.x), 0.0f);
                float h = fmaxf(fminf(gb.w, pbx.w) - fmaxf(gb.y, pbx.y), 0.0f);
                float inter = w * h;
                float iou = inter / fmaxf(gaa + pa - inter, 1e-6f);
                float x = srow[slab[g]];
                float c = cost_of_pair(iou, x, d2, s);
                if (c < best) { best = c; bg = g; rr2 = skip_radius2(best); }
            }
            gsel = bg;
        }
        float4 gb = sgt[gsel];
        float gaa = (gb.z - gb.x) * (gb.w - gb.y);
        float w = fmaxf(fminf(gb.z, pbx.z) - fmaxf(gb.x, pbx.x), 0.0f);
        float h = fmaxf(fminf(gb.w, pbx.w) - fmaxf(gb.y, pbx.y), 0.0f);
        float inter = w * h;
        float iou = inter / fmaxf(gaa + pa - inter, 1e-6f);

        lab = (float)slab[gsel];
        metr = iou;
        obox = gb;
    }

    out[bp]            = lab;
    out[BP + bp]       = 1.0f;
    reinterpret_cast<float4*>(out + 2 * (size_t)BP)[bp] = obox;
    out[6 * BP + bp]   = metr;
    out[7 * BP + bp]   = (d_fgpre[bp] > 0) ? 1.0f : 0.0f;
}

// ---------------- launch ----------------
extern "C" void kernel_launch(void* const* d_in, const int* in_sizes, int n_in,
                              void* d_out, int out_size) {
    const float* pred_bboxes = (const float*)d_in[0];
    const float* pred_scores = (const float*)d_in[1];
    const float* priors      = (const float*)d_in[2];
    const int*   gt_labels   = (const int*)  d_in[3];
    const float* gt_bboxes   = (const float*)d_in[4];
    const float* pad         = (const float*)d_in[5];

    int P = in_sizes[2] / 4;
    int B = in_sizes[0] / (P * 4);
    int G = in_sizes[4] / (B * 4);
    int C = in_sizes[1] / (B * P);
    float* out = (float*)d_out;
    int nch = (P + 31) / 32;

    dim3 gi((P + 255) / 256, B);
    init_kernel<<<gi, 256>>>(pred_bboxes, P);

    dim3 gr(G, B);
    validrect_kernel<<<gr, 128>>>(gt_bboxes, pad, P, G);

    inv13_kernel<<<B, 128>>>(P, nch);

    dim3 gs((P + 255) / 256, B);
    scatter_kernel<<<gs, 256>>>(pred_bboxes, P);

    dim3 gp(G, B);
    pair_kernel<<<gp, 128>>>(pred_bboxes, pred_scores, priors,
                             gt_labels, gt_bboxes, pad, P, G, C, nch);

    dim3 gf((P + 127) / 128, B);
    final_kernel<<<gf, 128>>>(pred_bboxes, pred_scores, priors,
                              gt_labels, gt_bboxes, out, P, G, C, B);
}

// round 16
// speedup vs baseline: 1.0440x; 1.0440x over previous
#include <cuda_runtime.h>
#include <math.h>
#include <stdint.h>

#define BB 16
#define GG 100
#define PP 8400
#define CC 80
#define TK 13
#define NBIN 64   // 8x8 spatial bins
#define NCHMAX ((PP + 31) / 32)

// ---------------- static scratch ----------------
__device__ int           d_fgpre[BB * PP];
__device__ int           d_mcount[BB * PP];
__device__ int           d_mg[BB * PP];
__device__ unsigned char d_valid[BB * PP];
__device__ float4        d_sorted[BB * PP];
__device__ int4          d_cmeta[BB * NCHMAX];   // float-bits chunk bboxes
__device__ int           d_inv13[BB * TK];
__device__ int           d_invcnt[BB];

// ---------------- sorted-list helpers ----------
template <int N>
__device__ __forceinline__ void ins_desc(float (&V)[N], int (&I)[N], float v, int idx) {
    if (v > V[N - 1] || (v == V[N - 1] && idx < I[N - 1])) {
#pragma unroll
        for (int k = 0; k < N; k++) {
            if (v > V[k] || (v == V[k] && idx < I[k])) {
                float tv = V[k]; int ti = I[k];
                V[k] = v; I[k] = idx;
                v = tv; idx = ti;
            }
        }
    }
}

template <int N>
__device__ __forceinline__ void ins_asc(float (&V)[N], int (&I)[N], float v, int idx) {
    if (v < V[N - 1] || (v == V[N - 1] && idx < I[N - 1])) {
#pragma unroll
        for (int k = 0; k < N; k++) {
            if (v < V[k] || (v == V[k] && idx < I[k])) {
                float tv = V[k]; int ti = I[k];
                V[k] = v; I[k] = idx;
                v = tv; idx = ti;
            }
        }
    }
}

template <int N>
__device__ __forceinline__ void ins_val(float (&V)[N], float v) {
    if (v > V[N - 1]) {
#pragma unroll
        for (int k = 0; k < N; k++) {
            if (v > V[k]) { float tv = V[k]; V[k] = v; v = tv; }
        }
    }
}

__device__ __forceinline__ float skip_radius2(float thr) {
    float rr = 3.0f + log10f(thr + 1e-6f) + 1e-3f;
    if (rr > 0.0f) return rr * rr;
    return (thr < 9e-4f) ? -1.0f : __int_as_float(0x7f800000);
}

__device__ __forceinline__ int binof(float4 t) {
    float xc = 0.5f * (t.x + t.z);
    float yc = 0.5f * (t.y + t.w);
    int bx = min(7, max(0, (int)(xc * (8.0f / 640.0f))));
    int by = min(7, max(0, (int)(yc * (8.0f / 640.0f))));
    return by * 8 + bx;
}

// block merge of 128 sorted ascending lists (value asc, idx asc)
__device__ __forceinline__ void merge_asc(float* s_v, int* s_i, int tid) {
    for (int off = 64; off >= 1; off >>= 1) {
        if (tid < off) {
            float ov[TK]; int oi[TK];
            int ia = tid * TK, ib = (tid + off) * TK, i = 0, j = 0;
#pragma unroll
            for (int k = 0; k < TK; k++) {
                float va = s_v[ia + i], vb = s_v[ib + j];
                int   na = s_i[ia + i], nb = s_i[ib + j];
                bool ta = (va < vb) || (va == vb && na < nb);
                if (ta) { ov[k] = va; oi[k] = na; i++; }
                else    { ov[k] = vb; oi[k] = nb; j++; }
            }
#pragma unroll
            for (int k = 0; k < TK; k++) { s_v[ia + k] = ov[k]; s_i[ia + k] = oi[k]; }
        }
        __syncthreads();
    }
}

// ---------------- prep: one block per batch, all binning in smem ----------------
__global__ __launch_bounds__(1024) void prep_kernel(const float* __restrict__ pred_bboxes,
                                                    int Pn, int nch) {
    int b = blockIdx.x, tid = threadIdx.x;
    __shared__ int scnt[NBIN];
    __shared__ int sbase[NBIN];
    __shared__ int scur[NBIN];
    __shared__ int4 smeta[NCHMAX];

    if (tid < NBIN) scnt[tid] = 0;
    for (int i = tid; i < nch; i += 1024)
        smeta[i] = make_int4(0x7fffffff, 0x7fffffff, 0x80000000, 0x80000000);

    // zero per-prior scratch (coalesced)
    for (int i = tid; i < Pn; i += 1024) {
        int bp = b * Pn + i;
        d_valid[bp]  = 0;
        d_fgpre[bp]  = 0;
        d_mcount[bp] = 0;
    }
    __syncthreads();

    const float4* pbsrc = reinterpret_cast<const float4*>(pred_bboxes) + (size_t)b * Pn;

    // pass 1: histogram
    for (int p = tid; p < Pn; p += 1024)
        atomicAdd(&scnt[binof(pbsrc[p])], 1);
    __syncthreads();

    // exclusive scan over 64 bins (Hillis-Steele in smem)
    if (tid < NBIN) sbase[tid] = scnt[tid];
    __syncthreads();
    for (int off = 1; off < NBIN; off <<= 1) {
        int v = 0;
        if (tid < NBIN && tid >= off) v = sbase[tid - off];
        __syncthreads();
        if (tid < NBIN) sbase[tid] += v;
        __syncthreads();
    }
    if (tid < NBIN) {
        sbase[tid] -= scnt[tid];   // inclusive -> exclusive
        scur[tid] = 0;
    }
    __syncthreads();

    // pass 2: scatter + smem chunk-bbox accumulation
    for (int p = tid; p < Pn; p += 1024) {
        float4 t = pbsrc[p];
        int bin = binof(t);
        int pos = sbase[bin] + atomicAdd(&scur[bin], 1);
        d_sorted[b * Pn + pos] = t;
        int* m = reinterpret_cast<int*>(&smeta[pos >> 5]);
        atomicMin(m + 0, __float_as_int(t.x));
        atomicMin(m + 1, __float_as_int(t.y));
        atomicMax(m + 2, __float_as_int(t.z));
        atomicMax(m + 3, __float_as_int(t.w));
    }
    __syncthreads();

    for (int i = tid; i < nch; i += 1024)
        d_cmeta[b * NCHMAX + i] = smeta[i];
}

// per (g,b): mark priors strictly inside the gt box via analytic grid rectangles.
__global__ void validrect_kernel(const float* __restrict__ gtb,
                                 const float* __restrict__ pad,
                                 int Pn, int Gn) {
    int g = blockIdx.x, b = blockIdx.y;
    if (pad[b * Gn + g] == 0.0f) return;
    const float gx1 = gtb[(b * Gn + g) * 4 + 0];
    const float gy1 = gtb[(b * Gn + g) * 4 + 1];
    const float gx2 = gtb[(b * Gn + g) * 4 + 2];
    const float gy2 = gtb[(b * Gn + g) * 4 + 3];
    const int   LW[3] = {80, 40, 20};
    const float LS[3] = {8.0f, 16.0f, 32.0f};
    const int   LBASE[3] = {0, 6400, 8000};
    unsigned char* vm = d_valid + b * Pn;
    int tid = threadIdx.x;
#pragma unroll
    for (int lvl = 0; lvl < 3; lvl++) {
        int W = LW[lvl]; float s = LS[lvl]; int base = LBASE[lvl];
        float inv_s = 1.0f / s;
        int c0 = max(0, (int)floorf(gx1 * inv_s - 0.5f));
        int c1 = min(W - 1, (int)ceilf(gx2 * inv_s - 0.5f));
        int r0 = max(0, (int)floorf(gy1 * inv_s - 0.5f));
        int r1 = min(W - 1, (int)ceilf(gy2 * inv_s - 0.5f));
        int nc = c1 - c0 + 1, nr = r1 - r0 + 1;
        if (nc <= 0 || nr <= 0) continue;
        int tot = nc * nr;
        for (int i = tid; i < tot; i += 128) {
            int rr = i / nc, cc = i - rr * nc;
            int col = c0 + cc, row = r0 + rr;
            float px = ((float)col + 0.5f) * s;
            float py = ((float)row + 0.5f) * s;
            if (px > gx1 && px < gx2 && py > gy1 && py < gy2)
                vm[base + row * W + col] = 1;
        }
    }
}

// per-batch: first-13 invalid prior indices. One block per batch, 128 threads.
__global__ void inv13_kernel(int Pn) {
    int b = blockIdx.x, tid = threadIdx.x;
    int lst[TK]; int cnt = 0;
    for (int p = tid; p < Pn && cnt < TK; p += 128)
        if (!d_valid[b * Pn + p]) lst[cnt++] = p;
#pragma unroll
    for (int k = 0; k < TK; k++) if (k >= cnt) lst[k] = 0x7fffffff;
    __shared__ int s_i[128 * TK];
#pragma unroll
    for (int k = 0; k < TK; k++) s_i[tid * TK + k] = lst[k];
    __syncthreads();
    for (int off = 64; off >= 1; off >>= 1) {
        if (tid < off) {
            int oi[TK];
            int ia = tid * TK, ib = (tid + off) * TK, i = 0, j = 0;
#pragma unroll
            for (int k = 0; k < TK; k++) {
                int na = s_i[ia + i], nb = s_i[ib + j];
                if (na <= nb) { oi[k] = na; i++; } else { oi[k] = nb; j++; }
            }
#pragma unroll
            for (int k = 0; k < TK; k++) s_i[ia + k] = oi[k];
        }
        __syncthreads();
    }
    if (tid == 0) {
        int S = 0;
#pragma unroll
        for (int k = 0; k < TK; k++) {
            d_inv13[b * TK + k] = s_i[k];
            if (s_i[k] != 0x7fffffff) S++;
        }
        d_invcnt[b] = S;
    }
}

// ---------------- main pair kernel ----------------
__global__ __launch_bounds__(128) void pair_kernel(
    const float* __restrict__ pred_bboxes,
    const float* __restrict__ pred_scores,
    const float* __restrict__ priors,
    const int*   __restrict__ gt_labels,
    const float* __restrict__ gt_bboxes,
    const float* __restrict__ pad,
    int Pn, int Gn, int Cn, int nch) {
    int g = blockIdx.x, b = blockIdx.y;
    if (pad[b * Gn + g] == 0.0f) return;

    const float gx1 = gt_bboxes[(b * Gn + g) * 4 + 0];
    const float gy1 = gt_bboxes[(b * Gn + g) * 4 + 1];
    const float gx2 = gt_bboxes[(b * Gn + g) * 4 + 2];
    const float gy2 = gt_bboxes[(b * Gn + g) * 4 + 3];
    const int   cid = gt_labels[b * Gn + g];
    const float ga  = (gx2 - gx1) * (gy2 - gy1);
    const float cx  = (gx1 + gx2) * 0.5f;
    const float cy  = (gy1 + gy2) * 0.5f;

    const float4*        pb  = reinterpret_cast<const float4*>(pred_bboxes) + (size_t)b * Pn;
    const float4*        pr4 = reinterpret_cast<const float4*>(priors);
    const float*         sc  = pred_scores + (size_t)b * Pn * Cn + cid;
    const unsigned char* vm  = d_valid + b * Pn;
    const int tid = threadIdx.x;
    const int warp = tid >> 5, lane = tid & 31;
    const float INFF = __int_as_float(0x7f800000);

    __shared__ float s_v[128 * TK];
    __shared__ int   s_i[128 * TK];
    __shared__ int   s_ks;
    __shared__ int   s_npos;
    __shared__ int   s_need2;

    // ======== Phase 1: top-13 iou; lane-parallel chunk-meta scan ========
    {
        float iv[TK];
#pragma unroll
        for (int k = 0; k < TK; k++) iv[k] = -INFF;
        const float4* sp = d_sorted + (size_t)b * Pn;
        const int4*   cm = d_cmeta + b * NCHMAX;
        int nbatch = (nch + 31) >> 5;
        for (int t = warp; t < nbatch; t += 4) {
            int cbase = t << 5;
            int c = cbase + lane;
            bool hit = false;
            if (c < nch) {
                int4 m4 = cm[c];
                float mx1 = __int_as_float(m4.x), my1 = __int_as_float(m4.y);
                float mx2 = __int_as_float(m4.z), my2 = __int_as_float(m4.w);
                hit = (mx1 < gx2 && mx2 > gx1 && my1 < gy2 && my2 > gy1);
            }
            unsigned mask = __ballot_sync(0xffffffffu, hit);
            while (mask) {
                int bit = __ffs(mask) - 1; mask &= mask - 1;
                int p = ((cbase + bit) << 5) + lane;
                if (p < Pn) {
                    float4 t4 = sp[p];
                    float pa = (t4.z - t4.x) * (t4.w - t4.y);
                    float w = fmaxf(fminf(gx2, t4.z) - fmaxf(gx1, t4.x), 0.0f);
                    float h = fmaxf(fminf(gy2, t4.w) - fmaxf(gy1, t4.y), 0.0f);
                    float inter = w * h;
                    float iou = __fdividef(inter, fmaxf(ga + pa - inter, 1e-6f));
                    ins_val(iv, iou);
                }
            }
        }
#pragma unroll
        for (int k = 0; k < TK; k++) s_v[tid * TK + k] = iv[k];
        __syncthreads();
        for (int off = 64; off >= 1; off >>= 1) {
            if (tid < off) {
                float ov[TK];
                int ia = tid * TK, ib = (tid + off) * TK, i = 0, j = 0;
#pragma unroll
                for (int k = 0; k < TK; k++) {
                    float va = s_v[ia + i], vb = s_v[ib + j];
                    if (va >= vb) { ov[k] = va; i++; } else { ov[k] = vb; j++; }
                }
#pragma unroll
                for (int k = 0; k < TK; k++) s_v[ia + k] = ov[k];
            }
            __syncthreads();
        }
        if (tid == 0) {
            float sum = 0.0f;
#pragma unroll
            for (int k = 0; k < TK; k++) sum += fmaxf(s_v[k], 0.0f);  // skipped pairs are iou==0
            int ks = (int)sum;
            if (ks < 1) ks = 1;
            if (ks > TK) ks = TK;
            s_ks = ks;
        }
        __syncthreads();
    }

    const int   LW[3] = {80, 40, 20};
    const float LS[3] = {8.0f, 16.0f, 32.0f};
    const int   LBASE[3] = {0, 6400, 8000};

    // ======== Phase 2: metric top-13 via gt-box grid rectangle ========
    {
        float mv[TK]; int mi[TK];
#pragma unroll
        for (int k = 0; k < TK; k++) { mv[k] = -INFF; mi[k] = 0x7fffffff; }
#pragma unroll
        for (int lvl = 0; lvl < 3; lvl++) {
            int W = LW[lvl]; float s = LS[lvl]; int base = LBASE[lvl];
            float inv_s = 1.0f / s;
            int c0 = max(0, (int)floorf(gx1 * inv_s - 0.5f));
            int c1 = min(W - 1, (int)ceilf(gx2 * inv_s - 0.5f));
            int r0 = max(0, (int)floorf(gy1 * inv_s - 0.5f));
            int r1 = min(W - 1, (int)ceilf(gy2 * inv_s - 0.5f));
            int nc = c1 - c0 + 1, nr = r1 - r0 + 1;
            if (nc <= 0 || nr <= 0) continue;
            int tot = nc * nr;
            for (int i = tid; i < tot; i += 128) {
                int rr = i / nc, cc = i - rr * nc;
                int col = c0 + cc, row = r0 + rr;
                float px = ((float)col + 0.5f) * s;
                float py = ((float)row + 0.5f) * s;
                if (px > gx1 && px < gx2 && py > gy1 && py < gy2) {
                    int p = base + row * W + col;
                    float4 t = pb[p];
                    float pa = (t.z - t.x) * (t.w - t.y);
                    float w = fmaxf(fminf(gx2, t.z) - fmaxf(gx1, t.x), 0.0f);
                    float h = fmaxf(fminf(gy2, t.w) - fmaxf(gy1, t.y), 0.0f);
                    float inter = w * h;
                    if (inter > 0.0f) {
                        float iou = inter / fmaxf(ga + pa - inter, 1e-6f);
                        float x = sc[(size_t)p * Cn];
                        float ax = fabsf(x);
                        float tt = expf(-ax);
                        float inv = 1.0f / (1.0f + tt);
                        float sig = (x >= 0.0f) ? inv : tt * inv;
                        float i2 = iou * iou;
                        float metric = sig * (i2 * i2 * i2);
                        ins_desc(mv, mi, metric, p);
                    }
                }
            }
        }
#pragma unroll
        for (int k = 0; k < TK; k++) { s_v[tid * TK + k] = mv[k]; s_i[tid * TK + k] = mi[k]; }
        __syncthreads();
        for (int off = 64; off >= 1; off >>= 1) {
            if (tid < off) {
                float ov[TK]; int oi[TK];
                int ia = tid * TK, ib = (tid + off) * TK, i = 0, j = 0;
#pragma unroll
                for (int k = 0; k < TK; k++) {
                    float va = s_v[ia + i], vb = s_v[ib + j];
                    int   na = s_i[ia + i], nb = s_i[ib + j];
                    bool ta = (va > vb) || (va == vb && na < nb);
                    if (ta) { ov[k] = va; oi[k] = na; i++; }
                    else    { ov[k] = vb; oi[k] = nb; j++; }
                }
#pragma unroll
                for (int k = 0; k < TK; k++) { s_v[ia + k] = ov[k]; s_i[ia + k] = oi[k]; }
            }
            __syncthreads();
        }
        if (tid == 0) {
            int np = 0;
#pragma unroll
            for (int k = 0; k < TK; k++) if (s_v[k] > 0.0f) np++;
            s_npos = np;
        }
        __syncthreads();
        if (tid < s_npos) {
            atomicAdd(&d_fgpre[b * Pn + s_i[tid]], 1);
        }
        if (tid == 0 && s_npos < TK) {
            // zero-metric fill: smallest global indices with metric==0; ing ones count
            int need = TK - s_npos;
            for (int p = 0; p < Pn && need > 0; p++) {
                float4 pr = pr4[p];
                bool ing = (pr.x > gx1) && (pr.x < gx2) && (pr.y > gy1) && (pr.y < gy2);
                bool pos = false;
                if (ing) {
                    float4 t = pb[p];
                    float pa = (t.z - t.x) * (t.w - t.y);
                    float w = fmaxf(fminf(gx2, t.z) - fmaxf(gx1, t.x), 0.0f);
                    float h = fmaxf(fminf(gy2, t.w) - fmaxf(gy1, t.y), 0.0f);
                    float inter = w * h;
                    if (inter > 0.0f) {
                        float iou = inter / fmaxf(ga + pa - inter, 1e-6f);
                        float x = sc[(size_t)p * Cn];
                        float ax = fabsf(x);
                        float tt = expf(-ax);
                        float inv = 1.0f / (1.0f + tt);
                        float sig = (x >= 0.0f) ? inv : tt * inv;
                        float i2 = iou * iou;
                        pos = (sig * (i2 * i2 * i2)) > 0.0f;
                    }
                }
                if (!pos) {
                    need--;
                    if (ing) atomicAdd(&d_fgpre[b * Pn + p], 1);
                }
            }
        }
        __syncthreads();
    }

    // ======== Phase 3: cost min-13, two-pass radius ========
    {
        float cv[TK]; int ci[TK];
#pragma unroll
        for (int k = 0; k < TK; k++) { cv[k] = INFF; ci[k] = 0x7fffffff; }
        const int S = d_invcnt[b];
        const bool fast = (S >= TK);
        const float R1 = 5.0013f;    // pass-1 radius (strides)
        const float R2 = 11.0013f;   // full radius: cost beyond > 1e8 sentinel

        if (fast) {
            for (int pass = 0; pass < 2; pass++) {
#pragma unroll
                for (int lvl = 0; lvl < 3; lvl++) {
                    int W = LW[lvl]; float s = LS[lvl]; int base = LBASE[lvl];
                    float inv_s = 1.0f / s;
                    float fc = cx * inv_s - 0.5f, fr = cy * inv_s - 0.5f;
                    float Rb = (pass == 0) ? R1 : R2;
                    int c0 = max(0, (int)floorf(fc - Rb));
                    int c1 = min(W - 1, (int)ceilf(fc + Rb));
                    int r0 = max(0, (int)floorf(fr - Rb));
                    int r1 = min(W - 1, (int)ceilf(fr + Rb));
                    int nc = c1 - c0 + 1, nr = r1 - r0 + 1;
                    if (nc <= 0 || nr <= 0) continue;
                    int tot = nc * nr;
                    float lim1 = R1 * R1 * s * s;
                    float lim2 = R2 * R2 * s * s;
                    for (int i = tid; i < tot; i += 128) {
                        int rr = i / nc, cc = i - rr * nc;
                        int col = c0 + cc, row = r0 + rr;
                        float px = ((float)col + 0.5f) * s;
                        float py = ((float)row + 0.5f) * s;
                        float dx = px - cx, dy = py - cy;
                        float d2 = dx * dx + dy * dy;
                        if (pass == 0) { if (d2 > lim1) continue; }
                        else           { if (d2 <= lim1 || d2 > lim2) continue; }
                        int p = base + row * W + col;
                        if (!vm[p]) continue;
                        float4 t = pb[p];
                        float pa = (t.z - t.x) * (t.w - t.y);
                        float w = fmaxf(fminf(gx2, t.z) - fmaxf(gx1, t.x), 0.0f);
                        float h = fmaxf(fminf(gy2, t.w) - fmaxf(gy1, t.y), 0.0f);
                        float inter = w * h;
                        float iou = inter / fmaxf(ga + pa - inter, 1e-6f);
                        float x = sc[(size_t)p * Cn];
                        float ax = fabsf(x);
                        float tt = expf(-ax);
                        float inv = 1.0f / (1.0f + tt);
                        float sig = (x >= 0.0f) ? inv : tt * inv;
                        float sp = fmaxf(x, 0.0f) + log1pf(tt);
                        float sca = iou - sig;
                        float cls = (sp - x * iou) * (sca * sca);
                        float icst = -3.0f * logf(iou + 1e-7f);
                        float dist = sqrtf(d2) / s;
                        float scp = expf((dist - 3.0f) * 2.302585092994046f);
                        ins_asc(cv, ci, cls + icst + scp, p);
                    }
                }

                // merge (and sentinel-merge) after this pass
#pragma unroll
                for (int k = 0; k < TK; k++) { s_v[tid * TK + k] = cv[k]; s_i[tid * TK + k] = ci[k]; }
                __syncthreads();
                merge_asc(s_v, s_i, tid);
                if (tid == 0) {
                    float av[TK]; int ai[TK];
#pragma unroll
                    for (int k = 0; k < TK; k++) { av[k] = s_v[k]; ai[k] = s_i[k]; }
                    int i = 0, j = 0;
#pragma unroll
                    for (int k = 0; k < TK; k++) {
                        float va = (i < TK) ? av[i] : INFF;
                        int   na = (i < TK) ? ai[i] : 0x7fffffff;
                        float vb = 1e8f;
                        int   nb = d_inv13[b * TK + j];
                        bool ta = (va < vb) || (va == vb && na < nb);
                        if (ta) { s_v[k] = va; s_i[k] = na; i++; }
                        else    { s_v[k] = vb; s_i[k] = nb; j++; }
                    }
                    // pass-1 sufficiency: priors beyond R1 have cost >= thr13?
                    s_need2 = (pass == 0 && skip_radius2(s_v[TK - 1]) > R1 * R1) ? 1 : 0;
                }
                __syncthreads();
                if (!s_need2) break;
            }
        } else {
            for (int p = tid; p < Pn; p += 128) {
                if (vm[p]) {
                    float4 pr = pr4[p];
                    float4 t = pb[p];
                    float pa = (t.z - t.x) * (t.w - t.y);
                    float w = fmaxf(fminf(gx2, t.z) - fmaxf(gx1, t.x), 0.0f);
                    float h = fmaxf(fminf(gy2, t.w) - fmaxf(gy1, t.y), 0.0f);
                    float inter = w * h;
                    float iou = inter / fmaxf(ga + pa - inter, 1e-6f);
                    float x = sc[(size_t)p * Cn];
                    float ax = fabsf(x);
                    float tt = expf(-ax);
                    float inv = 1.0f / (1.0f + tt);
                    float sig = (x >= 0.0f) ? inv : tt * inv;
                    float sp = fmaxf(x, 0.0f) + log1pf(tt);
                    float sca = iou - sig;
                    float cls = (sp - x * iou) * (sca * sca);
                    float icst = -3.0f * logf(iou + 1e-7f);
                    float dx = pr.x - cx, dy = pr.y - cy;
                    float dist = sqrtf(dx * dx + dy * dy) / pr.z;
                    float scp = expf((dist - 3.0f) * 2.302585092994046f);
                    ins_asc(cv, ci, cls + icst + scp, p);
                } else {
                    ins_asc(cv, ci, 1e8f, p);
                }
            }
#pragma unroll
            for (int k = 0; k < TK; k++) { s_v[tid * TK + k] = cv[k]; s_i[tid * TK + k] = ci[k]; }
            __syncthreads();
            merge_asc(s_v, s_i, tid);
        }

        if (tid < s_ks) {
            int p = s_i[tid];
            atomicAdd(&d_mcount[b * Pn + p], 1);
            d_mg[b * Pn + p] = g;
        }
    }
}

// ---------------- final resolution ----------------
__device__ __forceinline__ float cost_of_pair(
    float iou, float x, float d2, float s) {
    float ax  = fabsf(x);
    float t   = expf(-ax);
    float inv = 1.0f / (1.0f + t);
    float sig = (x >= 0.0f) ? inv : t * inv;
    float sp  = fmaxf(x, 0.0f) + log1pf(t);
    float sca = iou - sig;
    float cls = (sp - x * iou) * (sca * sca);
    float icst = -3.0f * logf(iou + 1e-7f);
    float dist = sqrtf(d2) / s;
    float scp  = expf((dist - 3.0f) * 2.302585092994046f);
    return cls + icst + scp;
}

__global__ __launch_bounds__(128) void final_kernel(
    const float* __restrict__ pred_bboxes,
    const float* __restrict__ pred_scores,
    const float* __restrict__ priors,
    const int*   __restrict__ gt_labels,
    const float* __restrict__ gt_bboxes,
    float* __restrict__ out,
    int Pn, int Gn, int Cn, int Bn) {
    int b = blockIdx.y;
    __shared__ float4 sgt[GG];
    __shared__ int    slab[GG];
    for (int i = threadIdx.x; i < Gn; i += blockDim.x) {
        sgt[i]  = reinterpret_cast<const float4*>(gt_bboxes + (size_t)b * Gn * 4)[i];
        slab[i] = gt_labels[b * Gn + i];
    }
    __syncthreads();

    int p = blockIdx.x * blockDim.x + threadIdx.x;
    if (p >= Pn) return;
    int bp = b * Pn + p;
    int BP = Bn * Pn;

    int cnt = d_mcount[bp];
    float lab = 80.0f, metr = 0.0f;
    float4 obox = make_float4(0.f, 0.f, 0.f, 0.f);

    if (cnt > 0) {
        float4 pbx = reinterpret_cast<const float4*>(pred_bboxes + (size_t)b * Pn * 4)[p];
        float pa = (pbx.z - pbx.x) * (pbx.w - pbx.y);
        int gsel;
        if (cnt == 1) {
            gsel = d_mg[bp];
        } else if (!d_valid[bp]) {
            gsel = 0;
        } else {
            float px = priors[p * 4 + 0], py = priors[p * 4 + 1], s = priors[p * 4 + 2];
            float s2 = s * s;
            const float* srow = pred_scores + ((size_t)b * Pn + p) * Cn;
            float best = __int_as_float(0x7f800000);
            float rr2  = __int_as_float(0x7f800000);
            int bg = 0;
            for (int g = 0; g < Gn; g++) {
                float4 gb = sgt[g];
                float gcx = (gb.x + gb.z) * 0.5f, gcy = (gb.y + gb.w) * 0.5f;
                float dx = px - gcx, dy = py - gcy;
                float d2 = dx * dx + dy * dy;
                if (d2 > rr2 * s2) continue;
                float gaa = (gb.z - gb.x) * (gb.w - gb.y);
                float w = fmaxf(fminf(gb.z, pbx.z) - fmaxf(gb.x, pbx.x), 0.0f);
                float h = fmaxf(fminf(gb.w, pbx.w) - fmaxf(gb.y, pbx.y), 0.0f);
                float inter = w * h;
                float iou = inter / fmaxf(gaa + pa - inter, 1e-6f);
                float x = srow[slab[g]];
                float c = cost_of_pair(iou, x, d2, s);
                if (c < best) { best = c; bg = g; rr2 = skip_radius2(best); }
            }
            gsel = bg;
        }
        float4 gb = sgt[gsel];
        float gaa = (gb.z - gb.x) * (gb.w - gb.y);
        float w = fmaxf(fminf(gb.z, pbx.z) - fmaxf(gb.x, pbx.x), 0.0f);
        float h = fmaxf(fminf(gb.w, pbx.w) - fmaxf(gb.y, pbx.y), 0.0f);
        float inter = w * h;
        float iou = inter / fmaxf(gaa + pa - inter, 1e-6f);

        lab = (float)slab[gsel];
        metr = iou;
        obox = gb;
    }

    out[bp]            = lab;
    out[BP + bp]       = 1.0f;
    reinterpret_cast<float4*>(out + 2 * (size_t)BP)[bp] = obox;
    out[6 * BP + bp]   = metr;
    out[7 * BP + bp]   = (d_fgpre[bp] > 0) ? 1.0f : 0.0f;
}

// ---------------- launch ----------------
extern "C" void kernel_launch(void* const* d_in, const int* in_sizes, int n_in,
                              void* d_out, int out_size) {
    const float* pred_bboxes = (const float*)d_in[0];
    const float* pred_scores = (const float*)d_in[1];
    const float* priors      = (const float*)d_in[2];
    const int*   gt_labels   = (const int*)  d_in[3];
    const float* gt_bboxes   = (const float*)d_in[4];
    const float* pad         = (const float*)d_in[5];

    int P = in_sizes[2] / 4;
    int B = in_sizes[0] / (P * 4);
    int G = in_sizes[4] / (B * 4);
    int C = in_sizes[1] / (B * P);
    float* out = (float*)d_out;
    int nch = (P + 31) / 32;

    prep_kernel<<<B, 1024>>>(pred_bboxes, P, nch);

    dim3 gr(G, B);
    validrect_kernel<<<gr, 128>>>(gt_bboxes, pad, P, G);

    inv13_kernel<<<B, 128>>>(P);

    dim3 gp(G, B);
    pair_kernel<<<gp, 128>>>(pred_bboxes, pred_scores, priors,
                             gt_labels, gt_bboxes, pad, P, G, C, nch);

    dim3 gf((P + 127) / 128, B);
    final_kernel<<<gf, 128>>>(pred_bboxes, pred_scores, priors,
                              gt_labels, gt_bboxes, out, P, G, C, B);
}